// round 4
// baseline (speedup 1.0000x reference)
#include <cuda_runtime.h>
#include <math.h>

#define SAMPLE_RATE_F 24000.0f
#define TWO_PI_F      6.2831855f      /* fl32(2*pi) */
#define HALF_STATIC   1200            /* ceil(5 * 0.01 * 24000) */
#define ATOM_THREADS  256

// PTX div.full.f32 — the non-IEEE full-range divide XLA:GPU emits for f32
// division. Bit-identical to the reference's t = idx / 24000 on this chip.
__device__ __forceinline__ float div_full(float a, float b) {
    float r;
    asm("div.full.f32 %0, %1, %2;" : "=f"(r) : "f"(a), "f"(b));
    return r;
}

// ---------------------------------------------------------------------------
// Accurate cos for |x| up to ~3000 rad (Cody-Waite mod 2*pi + even Taylor x^16).
// Abs error ~1.5e-6 rad — negligible vs the 1e-3 budget.
// ---------------------------------------------------------------------------
__device__ __forceinline__ float cos_accurate(float x) {
    const float INV_2PI = 0.15915494309189535f;
    const float C1 = 6.28318548202514648f;   // fl32(2*pi)
    const float C2 = -1.7484555e-07f;        // 2*pi - C1
    float k = rintf(__fmul_rn(x, INV_2PI));
    float r = fmaf(-k, C1, x);
    r = fmaf(-k, C2, r);
    float s = __fmul_rn(r, r);
    float p =              4.7794773e-14f;
    p = fmaf(p, s, -1.1470746e-11f);
    p = fmaf(p, s,  2.0876757e-09f);
    p = fmaf(p, s, -2.7557319e-07f);
    p = fmaf(p, s,  2.4801587e-05f);
    p = fmaf(p, s, -1.3888889e-03f);
    p = fmaf(p, s,  4.1666668e-02f);
    p = fmaf(p, s, -0.5f);
    return fmaf(p, s, 1.0f);
}

// Zero the output buffer (poisoned to 0xAA by the harness).
__global__ void gabor_zero_kernel(float* __restrict__ out, int n) {
    int i = blockIdx.x * blockDim.x + threadIdx.x;
    if (i < n) out[i] = 0.0f;
}

// One block per atom; threads stride the tight window and scatter atomically.
// Matches the XLA:GPU realization of the reference:
//   t     = div.full.f32(idx, 24000)            (bit-identical)
//   dt    = t - tau                              (Sterbenz-exact subtract)
//   z     = div.full.f32(dt, sigma)
//   phase = fl(2pi * fl(fl(om*dt) + fl(fl(0.5*gm)*dt)*dt)) + phi  (no FMA)
__global__ __launch_bounds__(ATOM_THREADS)
void gabor_render_kernel(const float* __restrict__ amplitude,
                         const float* __restrict__ tau,
                         const float* __restrict__ omega,
                         const float* __restrict__ sigma,
                         const float* __restrict__ phi,
                         const float* __restrict__ gamma,
                         float* __restrict__ out,
                         int num_samples) {
    const int atom = blockIdx.x;

    const float a  = amplitude[atom];
    const float tu = tau[atom];
    const float om = omega[atom];
    const float sg = sigma[atom];
    const float ph = phi[atom];
    const float gm = gamma[atom];

    // center = round-half-even(fl(tau * SR)), matching jnp.round
    const int   c  = __float2int_rn(__fmul_rn(tu, SAMPLE_RATE_F));
    const float r  = __fmul_rn(5.0f, sg);      // fl(5*sigma), mask radius
    const float g1 = __fmul_rn(0.5f, gm);      // fl(0.5*gamma)

    // Tight offset bounds, padded 1 sample; exact predicate below re-checks.
    const float delta0 = __fadd_rn(div_full((float)c, SAMPLE_RATE_F), -tu);
    int lo = (int)ceilf ((-r - delta0) * SAMPLE_RATE_F) - 1;
    int hi = (int)floorf(( r - delta0) * SAMPLE_RATE_F) + 1;
    lo = max(lo, max(-HALF_STATIC, -c));
    hi = min(hi, min( HALF_STATIC, num_samples - 1 - c));

    for (int off = lo + (int)threadIdx.x; off <= hi; off += ATOM_THREADS) {
        const int   idx = c + off;                          // in-bounds by construction
        const float t   = div_full((float)idx, SAMPLE_RATE_F);  // == ref bits
        const float dt  = __fadd_rn(t, -tu);                    // exact subtract
        if (fabsf(dt) <= r) {
            // envelope: exp(-0.5 * (dt/sigma)^2), div.full like the reference
            const float z   = div_full(dt, sg);
            const float env = __expf(__fmul_rn(-0.5f, __fmul_rn(z, z)));
            // phase, separately-rounded ops (XLA emits no FMA contraction)
            const float q     = __fmul_rn(__fmul_rn(g1, dt), dt);
            const float ssum  = __fadd_rn(__fmul_rn(om, dt), q);
            const float phase = __fadd_rn(__fmul_rn(TWO_PI_F, ssum), ph);
            const float val   = __fmul_rn(__fmul_rn(a, env), cos_accurate(phase));
            atomicAdd(&out[idx], val);
        }
    }
}

extern "C" void kernel_launch(void* const* d_in, const int* in_sizes, int n_in,
                              void* d_out, int out_size) {
    const float* amplitude = (const float*)d_in[0];
    const float* tau       = (const float*)d_in[1];
    const float* omega     = (const float*)d_in[2];
    const float* sigma     = (const float*)d_in[3];
    const float* phi       = (const float*)d_in[4];
    const float* gamma     = (const float*)d_in[5];
    float* out = (float*)d_out;

    const int num_atoms   = in_sizes[0];     // 16384
    const int num_samples = out_size;        // 240000

    {
        int threads = 256;
        int blocks  = (num_samples + threads - 1) / threads;
        gabor_zero_kernel<<<blocks, threads>>>(out, num_samples);
    }
    gabor_render_kernel<<<num_atoms, ATOM_THREADS>>>(
        amplitude, tau, omega, sigma, phi, gamma, out, num_samples);
}

// round 5
// speedup vs baseline: 1.0775x; 1.0775x over previous
#include <cuda_runtime.h>
#include <math.h>

#define SAMPLE_RATE_F 24000.0f
#define TWO_PI_F      6.2831855f      /* fl32(2*pi) */
#define HALF_STATIC   1200            /* ceil(5 * 0.01 * 24000) */
#define ATOM_THREADS  256
#define MAX_SAMPLES   240000

// Precomputed t[idx] = div.full.f32(idx, 24000) — bit-identical to the
// reference's t. Refilled every kernel_launch (deterministic), lives in L2.
__device__ float g_t_table[MAX_SAMPLES];

// PTX div.full.f32 — the non-IEEE divide XLA:GPU emits for f32 division.
__device__ __forceinline__ float div_full(float a, float b) {
    float r;
    asm("div.full.f32 %0, %1, %2;" : "=f"(r) : "f"(a), "f"(b));
    return r;
}

// Accurate cos for |x| up to ~3000 rad: Cody-Waite mod 2*pi + even Taylor
// through x^14 (abs err ~4e-6 at |r|=pi — far below the 1e-3 budget).
__device__ __forceinline__ float cos_accurate(float x) {
    const float INV_2PI = 0.15915494309189535f;
    const float C1 = 6.28318548202514648f;   // fl32(2*pi)
    const float C2 = -1.7484555e-07f;        // 2*pi - C1
    float k = rintf(__fmul_rn(x, INV_2PI));
    float r = fmaf(-k, C1, x);
    r = fmaf(-k, C2, r);
    float s = __fmul_rn(r, r);
    float p =             -1.1470746e-11f;   // -1/14!
    p = fmaf(p, s,  2.0876757e-09f);         //  1/12!
    p = fmaf(p, s, -2.7557319e-07f);         // -1/10!
    p = fmaf(p, s,  2.4801587e-05f);         //  1/8!
    p = fmaf(p, s, -1.3888889e-03f);         // -1/6!
    p = fmaf(p, s,  4.1666668e-02f);         //  1/4!
    p = fmaf(p, s, -0.5f);                   // -1/2!
    return fmaf(p, s, 1.0f);
}

// Init: zero the poisoned output AND fill the t-table in one pass.
__global__ void gabor_init_kernel(float* __restrict__ out, int n) {
    int i = blockIdx.x * blockDim.x + threadIdx.x;
    if (i < n) {
        out[i] = 0.0f;
        g_t_table[i] = div_full((float)i, SAMPLE_RATE_F);
    }
}

// One block per atom; threads stride the tight window and scatter atomically.
// t comes from the table (bit-exact), dt = fl(t - tau) matches the reference
// bit-for-bit, so the |dt| <= 5*sigma mask is exact. Envelope uses a
// per-block reciprocal (error ~4e-6 rel, amplitude-only).
__global__ __launch_bounds__(ATOM_THREADS)
void gabor_render_kernel(const float* __restrict__ amplitude,
                         const float* __restrict__ tau,
                         const float* __restrict__ omega,
                         const float* __restrict__ sigma,
                         const float* __restrict__ phi,
                         const float* __restrict__ gamma,
                         float* __restrict__ out,
                         int num_samples) {
    const int atom = blockIdx.x;

    const float a  = amplitude[atom];
    const float tu = tau[atom];
    const float om = omega[atom];
    const float sg = sigma[atom];
    const float ph = phi[atom];
    const float gm = gamma[atom];

    // center = round-half-even(fl(tau * SR)), matching jnp.round
    const int   c      = __float2int_rn(__fmul_rn(tu, SAMPLE_RATE_F));
    const float r      = __fmul_rn(5.0f, sg);   // fl(5*sigma), mask radius
    const float g1     = __fmul_rn(0.5f, gm);   // fl(0.5*gamma)
    const float inv_sg = __frcp_rn(sg);

    // Tight offset bounds, padded 1 sample; exact predicate below re-checks.
    const float delta0 = __fadd_rn(div_full((float)c, SAMPLE_RATE_F), -tu);
    int lo = (int)ceilf ((-r - delta0) * SAMPLE_RATE_F) - 1;
    int hi = (int)floorf(( r - delta0) * SAMPLE_RATE_F) + 1;
    lo = max(lo, max(-HALF_STATIC, -c));
    hi = min(hi, min( HALF_STATIC, num_samples - 1 - c));

    const float* __restrict__ tab = g_t_table + c;

    for (int off = lo + (int)threadIdx.x; off <= hi; off += ATOM_THREADS) {
        const float t  = __ldg(tab + off);          // == reference t bits
        const float dt = __fadd_rn(t, -tu);         // bit-exact dt
        if (fabsf(dt) <= r) {
            // envelope: exp(-0.5 * (dt/sigma)^2)
            const float z   = __fmul_rn(dt, inv_sg);
            const float env = __expf(__fmul_rn(-0.5f, __fmul_rn(z, z)));
            // phase, separately-rounded ops (XLA emits no FMA contraction)
            const float q     = __fmul_rn(__fmul_rn(g1, dt), dt);
            const float ssum  = __fadd_rn(__fmul_rn(om, dt), q);
            const float phase = __fadd_rn(__fmul_rn(TWO_PI_F, ssum), ph);
            const float val   = __fmul_rn(__fmul_rn(a, env), cos_accurate(phase));
            atomicAdd(&out[c + off], val);
        }
    }
}

extern "C" void kernel_launch(void* const* d_in, const int* in_sizes, int n_in,
                              void* d_out, int out_size) {
    const float* amplitude = (const float*)d_in[0];
    const float* tau       = (const float*)d_in[1];
    const float* omega     = (const float*)d_in[2];
    const float* sigma     = (const float*)d_in[3];
    const float* phi       = (const float*)d_in[4];
    const float* gamma     = (const float*)d_in[5];
    float* out = (float*)d_out;

    const int num_atoms   = in_sizes[0];     // 16384
    const int num_samples = out_size;        // 240000

    {
        int threads = 256;
        int blocks  = (num_samples + threads - 1) / threads;
        gabor_init_kernel<<<blocks, threads>>>(out, num_samples);
    }
    gabor_render_kernel<<<num_atoms, ATOM_THREADS>>>(
        amplitude, tau, omega, sigma, phi, gamma, out, num_samples);
}

// round 6
// speedup vs baseline: 1.3315x; 1.2358x over previous
#include <cuda_runtime.h>
#include <math.h>

#define SR_F        24000.0f
#define TWO_PI_F    6.2831855f          /* fl32(2*pi) */
#define INV_2PI_F   0.15915494309189535f
#define HALF_STATIC 1200                /* ceil(5 * 0.01 * 24000) */
#define THREADS     128
#define MAX_SAMPLES 240000
#define MAGIC_RN    12582912.0f         /* 1.5 * 2^23: round-to-nearest-int trick */
#define NEG_HALF_LOG2E 0.7213475204444817f  /* 0.5 * log2(e) */

// Precomputed t[idx] = div.full.f32(idx, 24000) — bit-identical to the
// reference's t (XLA:GPU lowers f32 divide to div.full). Refilled every call.
__device__ __align__(16) float g_t_table[MAX_SAMPLES];

__device__ __forceinline__ float div_full(float a, float b) {
    float r;
    asm("div.full.f32 %0, %1, %2;" : "=f"(r) : "f"(a), "f"(b));
    return r;
}
__device__ __forceinline__ float ex2_approx(float x) {
    float r;
    asm("ex2.approx.f32 %0, %1;" : "=f"(r) : "f"(x));
    return r;
}
__device__ __forceinline__ float cos_approx(float x) {   // |x| <= pi: ~1.3e-6 abs
    float r;
    asm("cos.approx.f32 %0, %1;" : "=f"(r) : "f"(x));
    return r;
}

// Init: zero output + fill t-table, vectorized (240000 % 4 == 0).
__global__ void gabor_init_kernel(float4* __restrict__ out4, int n4) {
    int i = blockIdx.x * blockDim.x + threadIdx.x;
    if (i < n4) {
        out4[i] = make_float4(0.f, 0.f, 0.f, 0.f);
        int b = i * 4;
        float4 tv;
        tv.x = div_full((float)(b    ), SR_F);
        tv.y = div_full((float)(b + 1), SR_F);
        tv.z = div_full((float)(b + 2), SR_F);
        tv.w = div_full((float)(b + 3), SR_F);
        reinterpret_cast<float4*>(g_t_table)[i] = tv;
    }
}

// One block per atom. Exact window [jlo, jhi] found by a uniform boundary
// scan with the bit-exact predicate |fl(t - tau)| <= fl(5*sigma); the inner
// loop then runs predicate-free:
//   dt   = t(table) - tau                      (bit-exact vs reference)
//   env  = ex2(-0.5*log2e/sg^2 * dt^2)
//   s    = om*dt + (0.5*gm)*dt^2 + phi/2pi     (cycles)
//   r    = s - rint(s)  (magic-constant)       -> ang = 2pi*r in [-pi, pi]
//   val  = a * env * cos.approx(ang)
__global__ __launch_bounds__(THREADS)
void gabor_render_kernel(const float* __restrict__ amplitude,
                         const float* __restrict__ tau,
                         const float* __restrict__ omega,
                         const float* __restrict__ sigma,
                         const float* __restrict__ phi,
                         const float* __restrict__ gamma,
                         float* __restrict__ out,
                         int num_samples) {
    const int atom = blockIdx.x;

    const float a  = amplitude[atom];
    const float tu = tau[atom];
    const float om = omega[atom];
    const float sg = sigma[atom];
    const float ph = phi[atom];
    const float gm = gamma[atom];

    const int   c     = __float2int_rn(__fmul_rn(tu, SR_F));  // jnp.round match
    const float r     = __fmul_rn(5.0f, sg);                  // fl(5*sigma)
    const float g2    = __fmul_rn(0.5f, gm);
    const float phi_c = __fmul_rn(ph, INV_2PI_F);             // phase in cycles
    const float inv_sg = __frcp_rn(sg);
    const float envc   = -__fmul_rn(NEG_HALF_LOG2E, __fmul_rn(inv_sg, inv_sg));

    // Conservative guesses (+/-2 pad), then exact refinement with the same
    // div.full bits the table holds — the mask matches the reference bitwise.
    const float delta0 = __fadd_rn(div_full((float)c, SR_F), -tu);
    int jlo = (int)ceilf ((-r - delta0) * SR_F) - 2;
    int jhi = (int)floorf(( r - delta0) * SR_F) + 2;
    jlo = max(jlo, max(-HALF_STATIC, -c));
    jhi = min(jhi, min( HALF_STATIC, num_samples - 1 - c));
    #pragma unroll 1
    while (jlo <= jhi &&
           fabsf(__fadd_rn(div_full((float)(c + jlo), SR_F), -tu)) > r) ++jlo;
    #pragma unroll 1
    while (jhi >= jlo &&
           fabsf(__fadd_rn(div_full((float)(c + jhi), SR_F), -tu)) > r) --jhi;

    const float* __restrict__ tp = g_t_table + c;
    float* __restrict__ op = out + c;

    for (int j = jlo + (int)threadIdx.x; j <= jhi; j += THREADS) {
        const float t   = __ldg(tp + j);
        const float dt  = __fadd_rn(t, -tu);            // bit-exact dt
        const float dt2 = __fmul_rn(dt, dt);
        const float env = ex2_approx(__fmul_rn(envc, dt2));
        const float s   = fmaf(om, dt, fmaf(g2, dt2, phi_c));   // cycles
        const float sb  = __fadd_rn(s, MAGIC_RN);
        const float k   = __fadd_rn(sb, -MAGIC_RN);     // rint(s)
        const float fr  = __fadd_rn(s, -k);             // exact, in [-0.5, 0.5]
        const float ang = __fmul_rn(TWO_PI_F, fr);      // [-pi, pi]
        const float val = __fmul_rn(__fmul_rn(a, env), cos_approx(ang));
        atomicAdd(op + j, val);
    }
}

extern "C" void kernel_launch(void* const* d_in, const int* in_sizes, int n_in,
                              void* d_out, int out_size) {
    const float* amplitude = (const float*)d_in[0];
    const float* tau       = (const float*)d_in[1];
    const float* omega     = (const float*)d_in[2];
    const float* sigma     = (const float*)d_in[3];
    const float* phi       = (const float*)d_in[4];
    const float* gamma     = (const float*)d_in[5];
    float* out = (float*)d_out;

    const int num_atoms   = in_sizes[0];     // 16384
    const int num_samples = out_size;        // 240000

    {
        int n4 = num_samples / 4;
        int threads = 256;
        int blocks  = (n4 + threads - 1) / threads;
        gabor_init_kernel<<<blocks, threads>>>((float4*)out, n4);
    }
    gabor_render_kernel<<<num_atoms, THREADS>>>(
        amplitude, tau, omega, sigma, phi, gamma, out, num_samples);
}

// round 7
// speedup vs baseline: 1.4980x; 1.1250x over previous
#include <cuda_runtime.h>
#include <math.h>

#define SR_F        24000.0f
#define TWO_PI_F    6.2831855f          /* fl32(2*pi) */
#define INV_2PI_F   0.15915494309189535f
#define HALF_STATIC 1200                /* ceil(5 * 0.01 * 24000) */
#define THREADS     128
#define MAX_SAMPLES 240000
#define MAGIC_RN    12582912.0f         /* 1.5 * 2^23 round-to-int trick */
#define HALF_LOG2E  0.7213475204444817f /* 0.5 * log2(e) */

// Precomputed t[idx] = div.full.f32(idx, 24000) — bit-identical to the
// reference's t (XLA:GPU lowers f32 divide to div.full). Refilled every call.
__device__ __align__(16) float g_t_table[MAX_SAMPLES];

__device__ __forceinline__ float div_full(float a, float b) {
    float r;
    asm("div.full.f32 %0, %1, %2;" : "=f"(r) : "f"(a), "f"(b));
    return r;
}
__device__ __forceinline__ float ex2_approx(float x) {
    float r;
    asm("ex2.approx.f32 %0, %1;" : "=f"(r) : "f"(x));
    return r;
}
__device__ __forceinline__ float cos_approx(float x) {   // |x| <= pi: ~1.3e-6 abs
    float r;
    asm("cos.approx.f32 %0, %1;" : "=f"(r) : "f"(x));
    return r;
}

// Init: zero output + fill t-table, vectorized (240000 % 4 == 0).
__global__ void gabor_init_kernel(float4* __restrict__ out4, int n4) {
    int i = blockIdx.x * blockDim.x + threadIdx.x;
    if (i < n4) {
        out4[i] = make_float4(0.f, 0.f, 0.f, 0.f);
        int b = i * 4;
        float4 tv;
        tv.x = div_full((float)(b    ), SR_F);
        tv.y = div_full((float)(b + 1), SR_F);
        tv.z = div_full((float)(b + 2), SR_F);
        tv.w = div_full((float)(b + 3), SR_F);
        reinterpret_cast<float4*>(g_t_table)[i] = tv;
    }
}

// Per-lane evaluation: dt bit-exact, env via EX2, phase reduced in cycles.
__device__ __forceinline__ float gabor_eval(float t, float tu, float envc,
                                            float om, float g2, float phi_c,
                                            float a) {
    const float dt  = __fadd_rn(t, -tu);
    const float dt2 = __fmul_rn(dt, dt);
    const float env = ex2_approx(__fmul_rn(envc, dt2));
    const float s   = fmaf(om, dt, fmaf(g2, dt2, phi_c));   // cycles
    const float k   = __fadd_rn(__fadd_rn(s, MAGIC_RN), -MAGIC_RN); // rint(s)
    const float ang = __fmul_rn(TWO_PI_F, __fadd_rn(s, -k));        // [-pi,pi]
    return __fmul_rn(__fmul_rn(a, env), cos_approx(ang));
}

// One block per atom. Exact window [loA, hiA] (absolute samples) found by a
// uniform boundary scan with the bit-exact predicate |fl(t-tau)| <= fl(5*sg);
// the loop runs over 4-aligned float4 vectors, masking only boundary vectors.
__global__ __launch_bounds__(THREADS)
void gabor_render_kernel(const float* __restrict__ amplitude,
                         const float* __restrict__ tau,
                         const float* __restrict__ omega,
                         const float* __restrict__ sigma,
                         const float* __restrict__ phi,
                         const float* __restrict__ gamma,
                         float* __restrict__ out,
                         int num_samples) {
    const int atom = blockIdx.x;

    const float a  = amplitude[atom];
    const float tu = tau[atom];
    const float om = omega[atom];
    const float sg = sigma[atom];
    const float ph = phi[atom];
    const float gm = gamma[atom];

    const int   c     = __float2int_rn(__fmul_rn(tu, SR_F));  // jnp.round match
    const float r     = __fmul_rn(5.0f, sg);                  // fl(5*sigma)
    const float g2    = __fmul_rn(0.5f, gm);
    const float phi_c = __fmul_rn(ph, INV_2PI_F);
    const float inv_sg = __frcp_rn(sg);
    const float envc   = -__fmul_rn(HALF_LOG2E, __fmul_rn(inv_sg, inv_sg));

    // Conservative bounds (+/-2 pad), then exact refinement (bit-exact mask).
    const float delta0 = __fadd_rn(div_full((float)c, SR_F), -tu);
    int jlo = (int)ceilf ((-r - delta0) * SR_F) - 2;
    int jhi = (int)floorf(( r - delta0) * SR_F) + 2;
    jlo = max(jlo, max(-HALF_STATIC, -c));
    jhi = min(jhi, min( HALF_STATIC, num_samples - 1 - c));
    #pragma unroll 1
    while (jlo <= jhi &&
           fabsf(__fadd_rn(div_full((float)(c + jlo), SR_F), -tu)) > r) ++jlo;
    #pragma unroll 1
    while (jhi >= jlo &&
           fabsf(__fadd_rn(div_full((float)(c + jhi), SR_F), -tu)) > r) --jhi;
    if (jlo > jhi) return;

    const int loA = c + jlo;            // first active sample (absolute)
    const int hiA = c + jhi;            // last active sample
    const int lo4 = loA & ~3;           // 4-aligned vector start (>= 0)
    const int hi4 = hiA & ~3;           // last vector start (hi4+3 <= 239999)

    for (int i0 = lo4 + 4 * (int)threadIdx.x; i0 <= hi4; i0 += 4 * THREADS) {
        const float4 tv = __ldg(reinterpret_cast<const float4*>(g_t_table + i0));
        float4 val;
        val.x = gabor_eval(tv.x, tu, envc, om, g2, phi_c, a);
        val.y = gabor_eval(tv.y, tu, envc, om, g2, phi_c, a);
        val.z = gabor_eval(tv.z, tu, envc, om, g2, phi_c, a);
        val.w = gabor_eval(tv.w, tu, envc, om, g2, phi_c, a);
        if (i0 < loA || i0 + 3 > hiA) {          // boundary vectors only
            if (i0 + 0 < loA || i0 + 0 > hiA) val.x = 0.0f;
            if (i0 + 1 < loA || i0 + 1 > hiA) val.y = 0.0f;
            if (i0 + 2 < loA || i0 + 2 > hiA) val.z = 0.0f;
            if (i0 + 3 < loA || i0 + 3 > hiA) val.w = 0.0f;
        }
        atomicAdd(reinterpret_cast<float4*>(out + i0), val);   // RED.128
    }
}

extern "C" void kernel_launch(void* const* d_in, const int* in_sizes, int n_in,
                              void* d_out, int out_size) {
    const float* amplitude = (const float*)d_in[0];
    const float* tau       = (const float*)d_in[1];
    const float* omega     = (const float*)d_in[2];
    const float* sigma     = (const float*)d_in[3];
    const float* phi       = (const float*)d_in[4];
    const float* gamma     = (const float*)d_in[5];
    float* out = (float*)d_out;

    const int num_atoms   = in_sizes[0];     // 16384
    const int num_samples = out_size;        // 240000

    {
        int n4 = num_samples / 4;
        int threads = 256;
        int blocks  = (n4 + threads - 1) / threads;
        gabor_init_kernel<<<blocks, threads>>>((float4*)out, n4);
    }
    gabor_render_kernel<<<num_atoms, THREADS>>>(
        amplitude, tau, omega, sigma, phi, gamma, out, num_samples);
}

// round 8
// speedup vs baseline: 1.6396x; 1.0945x over previous
#include <cuda_runtime.h>
#include <math.h>

#define SR_F        24000.0f
#define TWO_PI_F    6.2831855f          /* fl32(2*pi) */
#define INV_2PI_F   0.15915494309189535f
#define HALF_STATIC 1200                /* ceil(5 * 0.01 * 24000) */
#define THREADS     128
#define ATOMS_PER_BLOCK 4               /* one warp per atom */
#define MAX_SAMPLES 240000
#define MAGIC_RN    12582912.0f         /* 1.5 * 2^23 round-to-int trick */
#define HALF_LOG2E  0.7213475204444817f /* 0.5 * log2(e) */

// Precomputed t[idx] = div.full.f32(idx, 24000) — bit-identical to the
// reference's t (XLA:GPU lowers f32 divide to div.full). Refilled every call.
__device__ __align__(16) float g_t_table[MAX_SAMPLES];

__device__ __forceinline__ float div_full(float a, float b) {
    float r;
    asm("div.full.f32 %0, %1, %2;" : "=f"(r) : "f"(a), "f"(b));
    return r;
}
__device__ __forceinline__ float ex2_approx(float x) {
    float r;
    asm("ex2.approx.f32 %0, %1;" : "=f"(r) : "f"(x));
    return r;
}
__device__ __forceinline__ float cos_approx(float x) {   // |x| <= pi: ~1.3e-6 abs
    float r;
    asm("cos.approx.f32 %0, %1;" : "=f"(r) : "f"(x));
    return r;
}

// Init: zero output + fill t-table, vectorized (240000 % 4 == 0).
__global__ void gabor_init_kernel(float4* __restrict__ out4, int n4) {
    int i = blockIdx.x * blockDim.x + threadIdx.x;
    if (i < n4) {
        out4[i] = make_float4(0.f, 0.f, 0.f, 0.f);
        int b = i * 4;
        float4 tv;
        tv.x = div_full((float)(b    ), SR_F);
        tv.y = div_full((float)(b + 1), SR_F);
        tv.z = div_full((float)(b + 2), SR_F);
        tv.w = div_full((float)(b + 3), SR_F);
        reinterpret_cast<float4*>(g_t_table)[i] = tv;
    }
}

// Per-lane evaluation: dt bit-exact, env via EX2, phase reduced in cycles.
__device__ __forceinline__ float gabor_eval(float t, float tu, float envc,
                                            float om, float g2, float phi_c,
                                            float a) {
    const float dt  = __fadd_rn(t, -tu);
    const float dt2 = __fmul_rn(dt, dt);
    const float env = ex2_approx(__fmul_rn(envc, dt2));
    const float s   = fmaf(om, dt, fmaf(g2, dt2, phi_c));   // cycles
    const float k   = __fadd_rn(__fadd_rn(s, MAGIC_RN), -MAGIC_RN); // rint(s)
    const float ang = __fmul_rn(TWO_PI_F, __fadd_rn(s, -k));        // [-pi,pi]
    return __fmul_rn(__fmul_rn(a, env), cos_approx(ang));
}

// One WARP per atom (4 atoms per 128-thread block): the per-atom prologue
// (param loads, div.full bounds scan) issues once per atom instead of 4x.
// Exact window [loA, hiA] via bit-exact |fl(t-tau)| <= fl(5*sigma) scan;
// inner loop runs 4-aligned float4 vectors, masking only boundary vectors.
__global__ __launch_bounds__(THREADS)
void gabor_render_kernel(const float* __restrict__ amplitude,
                         const float* __restrict__ tau,
                         const float* __restrict__ omega,
                         const float* __restrict__ sigma,
                         const float* __restrict__ phi,
                         const float* __restrict__ gamma,
                         float* __restrict__ out,
                         int num_samples) {
    const int wid  = (int)threadIdx.x >> 5;
    const int lane = (int)threadIdx.x & 31;
    const int atom = blockIdx.x * ATOMS_PER_BLOCK + wid;

    const float a  = __ldg(amplitude + atom);
    const float tu = __ldg(tau + atom);
    const float om = __ldg(omega + atom);
    const float sg = __ldg(sigma + atom);
    const float ph = __ldg(phi + atom);
    const float gm = __ldg(gamma + atom);

    const int   c     = __float2int_rn(__fmul_rn(tu, SR_F));  // jnp.round match
    const float r     = __fmul_rn(5.0f, sg);                  // fl(5*sigma)
    const float g2    = __fmul_rn(0.5f, gm);
    const float phi_c = __fmul_rn(ph, INV_2PI_F);
    const float inv_sg = __frcp_rn(sg);
    const float envc   = -__fmul_rn(HALF_LOG2E, __fmul_rn(inv_sg, inv_sg));

    // Conservative bounds (+/-2 pad), then exact refinement (bit-exact mask).
    const float delta0 = __fadd_rn(div_full((float)c, SR_F), -tu);
    int jlo = (int)ceilf ((-r - delta0) * SR_F) - 2;
    int jhi = (int)floorf(( r - delta0) * SR_F) + 2;
    jlo = max(jlo, max(-HALF_STATIC, -c));
    jhi = min(jhi, min( HALF_STATIC, num_samples - 1 - c));
    #pragma unroll 1
    while (jlo <= jhi &&
           fabsf(__fadd_rn(div_full((float)(c + jlo), SR_F), -tu)) > r) ++jlo;
    #pragma unroll 1
    while (jhi >= jlo &&
           fabsf(__fadd_rn(div_full((float)(c + jhi), SR_F), -tu)) > r) --jhi;
    if (jlo > jhi) return;

    const int loA = c + jlo;            // first active sample (absolute)
    const int hiA = c + jhi;            // last active sample
    const int lo4 = loA & ~3;           // 4-aligned vector start (>= 0)
    const int hi4 = hiA & ~3;           // last vector start (hi4+3 <= 239999)

    for (int i0 = lo4 + 4 * lane; i0 <= hi4; i0 += 4 * 32) {
        const float4 tv = __ldg(reinterpret_cast<const float4*>(g_t_table + i0));
        float4 val;
        val.x = gabor_eval(tv.x, tu, envc, om, g2, phi_c, a);
        val.y = gabor_eval(tv.y, tu, envc, om, g2, phi_c, a);
        val.z = gabor_eval(tv.z, tu, envc, om, g2, phi_c, a);
        val.w = gabor_eval(tv.w, tu, envc, om, g2, phi_c, a);
        if (i0 < loA || i0 + 3 > hiA) {          // boundary vectors only
            if (i0 + 0 < loA || i0 + 0 > hiA) val.x = 0.0f;
            if (i0 + 1 < loA || i0 + 1 > hiA) val.y = 0.0f;
            if (i0 + 2 < loA || i0 + 2 > hiA) val.z = 0.0f;
            if (i0 + 3 < loA || i0 + 3 > hiA) val.w = 0.0f;
        }
        atomicAdd(reinterpret_cast<float4*>(out + i0), val);   // RED.128
    }
}

extern "C" void kernel_launch(void* const* d_in, const int* in_sizes, int n_in,
                              void* d_out, int out_size) {
    const float* amplitude = (const float*)d_in[0];
    const float* tau       = (const float*)d_in[1];
    const float* omega     = (const float*)d_in[2];
    const float* sigma     = (const float*)d_in[3];
    const float* phi       = (const float*)d_in[4];
    const float* gamma     = (const float*)d_in[5];
    float* out = (float*)d_out;

    const int num_atoms   = in_sizes[0];     // 16384
    const int num_samples = out_size;        // 240000

    {
        int n4 = num_samples / 4;
        int threads = 256;
        int blocks  = (n4 + threads - 1) / threads;
        gabor_init_kernel<<<blocks, threads>>>((float4*)out, n4);
    }
    gabor_render_kernel<<<num_atoms / ATOMS_PER_BLOCK, THREADS>>>(
        amplitude, tau, omega, sigma, phi, gamma, out, num_samples);
}

// round 9
// speedup vs baseline: 1.7823x; 1.0871x over previous
#include <cuda_runtime.h>
#include <math.h>

#define SR_F        24000.0f
#define TWO_PI_F    6.2831855f          /* fl32(2*pi) */
#define PI_F        3.1415927f          /* fl32(pi) */
#define HALF_STATIC 1200                /* ceil(5 * 0.01 * 24000) */
#define THREADS     128
#define ATOMS_PER_BLOCK 4               /* one warp per atom */
#define MAX_SAMPLES 240000
#define HALF_LOG2E  0.7213475204444817f /* 0.5 * log2(e) */

// Precomputed t[idx] = div.full.f32(idx, 24000) — bit-identical to the
// reference's t (XLA:GPU lowers f32 divide to div.full). Refilled every call.
__device__ __align__(16) float g_t_table[MAX_SAMPLES];

__device__ __forceinline__ float div_full(float a, float b) {
    float r;
    asm("div.full.f32 %0, %1, %2;" : "=f"(r) : "f"(a), "f"(b));
    return r;
}
__device__ __forceinline__ float ex2_approx(float x) {
    float r;
    asm("ex2.approx.f32 %0, %1;" : "=f"(r) : "f"(x));
    return r;
}
// MUFU.COS with hardware argument reduction; |arg| <= ~2700 rad here, where
// the internal reduction error is ~ulp(arg) ≈ 1e-4 rad worst-case — well
// inside the 1e-3 rel-err budget.
__device__ __forceinline__ float cos_approx(float x) {
    float r;
    asm("cos.approx.f32 %0, %1;" : "=f"(r) : "f"(x));
    return r;
}

// Init: zero output + fill t-table, vectorized (240000 % 4 == 0).
__global__ void gabor_init_kernel(float4* __restrict__ out4, int n4) {
    int i = blockIdx.x * blockDim.x + threadIdx.x;
    if (i < n4) {
        out4[i] = make_float4(0.f, 0.f, 0.f, 0.f);
        int b = i * 4;
        float4 tv;
        tv.x = div_full((float)(b    ), SR_F);
        tv.y = div_full((float)(b + 1), SR_F);
        tv.z = div_full((float)(b + 2), SR_F);
        tv.w = div_full((float)(b + 3), SR_F);
        reinterpret_cast<float4*>(g_t_table)[i] = tv;
    }
}

// Per-lane evaluation: dt bit-exact; env via EX2; phase directly in radians
// (om_w = 2*pi*omega, g_w = pi*gamma precomputed per atom), MUFU.COS reduces.
__device__ __forceinline__ float gabor_eval(float t, float tu, float envc,
                                            float om_w, float g_w, float ph,
                                            float a) {
    const float dt    = __fadd_rn(t, -tu);
    const float dt2   = __fmul_rn(dt, dt);
    const float env   = ex2_approx(__fmul_rn(envc, dt2));
    const float phase = fmaf(om_w, dt, fmaf(g_w, dt2, ph));
    return __fmul_rn(__fmul_rn(a, env), cos_approx(phase));
}

// One WARP per atom (4 atoms per 128-thread block). Exact window [loA, hiA]
// via bit-exact |fl(t-tau)| <= fl(5*sigma) boundary scan; inner loop runs
// 4-aligned float4 vectors, masking only boundary vectors.
__global__ __launch_bounds__(THREADS)
void gabor_render_kernel(const float* __restrict__ amplitude,
                         const float* __restrict__ tau,
                         const float* __restrict__ omega,
                         const float* __restrict__ sigma,
                         const float* __restrict__ phi,
                         const float* __restrict__ gamma,
                         float* __restrict__ out,
                         int num_samples) {
    const int wid  = (int)threadIdx.x >> 5;
    const int lane = (int)threadIdx.x & 31;
    const int atom = blockIdx.x * ATOMS_PER_BLOCK + wid;

    const float a  = __ldg(amplitude + atom);
    const float tu = __ldg(tau + atom);
    const float om = __ldg(omega + atom);
    const float sg = __ldg(sigma + atom);
    const float ph = __ldg(phi + atom);
    const float gm = __ldg(gamma + atom);

    const int   c    = __float2int_rn(__fmul_rn(tu, SR_F));  // jnp.round match
    const float r    = __fmul_rn(5.0f, sg);                  // fl(5*sigma)
    const float om_w = __fmul_rn(TWO_PI_F, om);              // rad/s
    const float g_w  = __fmul_rn(PI_F, gm);                  // rad/s^2 (2pi*0.5*gm)
    const float inv_sg = __frcp_rn(sg);
    const float envc   = -__fmul_rn(HALF_LOG2E, __fmul_rn(inv_sg, inv_sg));

    // Conservative bounds (+/-2 pad), then exact refinement (bit-exact mask).
    const float delta0 = __fadd_rn(div_full((float)c, SR_F), -tu);
    int jlo = (int)ceilf ((-r - delta0) * SR_F) - 2;
    int jhi = (int)floorf(( r - delta0) * SR_F) + 2;
    jlo = max(jlo, max(-HALF_STATIC, -c));
    jhi = min(jhi, min( HALF_STATIC, num_samples - 1 - c));
    #pragma unroll 1
    while (jlo <= jhi &&
           fabsf(__fadd_rn(div_full((float)(c + jlo), SR_F), -tu)) > r) ++jlo;
    #pragma unroll 1
    while (jhi >= jlo &&
           fabsf(__fadd_rn(div_full((float)(c + jhi), SR_F), -tu)) > r) --jhi;
    if (jlo > jhi) return;

    const int loA = c + jlo;            // first active sample (absolute)
    const int hiA = c + jhi;            // last active sample
    const int lo4 = loA & ~3;           // 4-aligned vector start (>= 0)
    const int hi4 = hiA & ~3;           // last vector start (hi4+3 <= 239999)

    for (int i0 = lo4 + 4 * lane; i0 <= hi4; i0 += 4 * 32) {
        const float4 tv = __ldg(reinterpret_cast<const float4*>(g_t_table + i0));
        float4 val;
        val.x = gabor_eval(tv.x, tu, envc, om_w, g_w, ph, a);
        val.y = gabor_eval(tv.y, tu, envc, om_w, g_w, ph, a);
        val.z = gabor_eval(tv.z, tu, envc, om_w, g_w, ph, a);
        val.w = gabor_eval(tv.w, tu, envc, om_w, g_w, ph, a);
        if (i0 < loA || i0 + 3 > hiA) {          // boundary vectors only
            if (i0 + 0 < loA || i0 + 0 > hiA) val.x = 0.0f;
            if (i0 + 1 < loA || i0 + 1 > hiA) val.y = 0.0f;
            if (i0 + 2 < loA || i0 + 2 > hiA) val.z = 0.0f;
            if (i0 + 3 < loA || i0 + 3 > hiA) val.w = 0.0f;
        }
        atomicAdd(reinterpret_cast<float4*>(out + i0), val);   // RED.128
    }
}

extern "C" void kernel_launch(void* const* d_in, const int* in_sizes, int n_in,
                              void* d_out, int out_size) {
    const float* amplitude = (const float*)d_in[0];
    const float* tau       = (const float*)d_in[1];
    const float* omega     = (const float*)d_in[2];
    const float* sigma     = (const float*)d_in[3];
    const float* phi       = (const float*)d_in[4];
    const float* gamma     = (const float*)d_in[5];
    float* out = (float*)d_out;

    const int num_atoms   = in_sizes[0];     // 16384
    const int num_samples = out_size;        // 240000

    {
        int n4 = num_samples / 4;
        int threads = 256;
        int blocks  = (n4 + threads - 1) / threads;
        gabor_init_kernel<<<blocks, threads>>>((float4*)out, n4);
    }
    gabor_render_kernel<<<num_atoms / ATOMS_PER_BLOCK, THREADS>>>(
        amplitude, tau, omega, sigma, phi, gamma, out, num_samples);
}

// round 10
// speedup vs baseline: 1.8801x; 1.0548x over previous
#include <cuda_runtime.h>
#include <math.h>

#define SR_F        24000.0f
#define INV_SR_F    (1.0f / 24000.0f)
#define TWO_PI_F    6.2831855f          /* fl32(2*pi) */
#define PI_F        3.1415927f          /* fl32(pi) */
#define HALF_STATIC 1200                /* ceil(5 * 0.01 * 24000) */
#define THREADS     128
#define ATOMS_PER_BLOCK 4               /* one warp per atom */
#define MAX_SAMPLES 240000
#define HALF_LOG2E  0.7213475204444817f /* 0.5 * log2(e) */

// Precomputed t[idx] = div.full.f32(idx, 24000) — bit-identical to the
// reference's t (XLA:GPU lowers f32 divide to div.full). Refilled every call.
__device__ __align__(16) float g_t_table[MAX_SAMPLES];

__device__ __forceinline__ float div_full(float a, float b) {
    float r;
    asm("div.full.f32 %0, %1, %2;" : "=f"(r) : "f"(a), "f"(b));
    return r;
}
__device__ __forceinline__ float ex2_approx(float x) {
    float r;
    asm("ex2.approx.f32 %0, %1;" : "=f"(r) : "f"(x));
    return r;
}
__device__ __forceinline__ float cos_approx(float x) {
    float r;
    asm("cos.approx.f32 %0, %1;" : "=f"(r) : "f"(x));
    return r;
}

// Init: zero output + fill t-table, vectorized (240000 % 4 == 0).
__global__ void gabor_init_kernel(float4* __restrict__ out4, int n4) {
    int i = blockIdx.x * blockDim.x + threadIdx.x;
    if (i < n4) {
        out4[i] = make_float4(0.f, 0.f, 0.f, 0.f);
        int b = i * 4;
        float4 tv;
        tv.x = div_full((float)(b    ), SR_F);
        tv.y = div_full((float)(b + 1), SR_F);
        tv.z = div_full((float)(b + 2), SR_F);
        tv.w = div_full((float)(b + 3), SR_F);
        reinterpret_cast<float4*>(g_t_table)[i] = tv;
    }
}

// Per-lane evaluation, amplitude folded into the transcendentals:
//   env' = ex2(envc*dt^2 + log2|a|)   (= |a| * exp(-dt^2 / (2 sg^2)))
//   val  = env' * cos(om_w*dt + g_w*dt^2 + ph')   (ph' absorbs sign(a))
// 8 issue slots per sample. Samples just outside the true 5-sigma mask carry
// env <= e^-12.5 ~ 3.7e-6 * |a| — adding them unmasked is a ~1e-7 rel effect.
__device__ __forceinline__ float gabor_eval(float t, float tu, float envc,
                                            float l2a, float om_w, float g_w,
                                            float ph) {
    const float dt    = __fadd_rn(t, -tu);          // bit-exact dt
    const float dt2   = __fmul_rn(dt, dt);
    const float env   = ex2_approx(fmaf(envc, dt2, l2a));
    const float phase = fmaf(om_w, dt, fmaf(g_w, dt2, ph));
    return __fmul_rn(env, cos_approx(phase));
}

// One WARP per atom. Conservative (+/-2 padded) window bounds — no exact
// boundary scan, no per-vector masking (edge samples are ~e^-12.5 in env).
__global__ __launch_bounds__(THREADS)
void gabor_render_kernel(const float* __restrict__ amplitude,
                         const float* __restrict__ tau,
                         const float* __restrict__ omega,
                         const float* __restrict__ sigma,
                         const float* __restrict__ phi,
                         const float* __restrict__ gamma,
                         float* __restrict__ out,
                         int num_samples) {
    const int wid  = (int)threadIdx.x >> 5;
    const int lane = (int)threadIdx.x & 31;
    const int atom = blockIdx.x * ATOMS_PER_BLOCK + wid;

    const float a  = __ldg(amplitude + atom);
    const float tu = __ldg(tau + atom);
    const float om = __ldg(omega + atom);
    const float sg = __ldg(sigma + atom);
    const float ph = __ldg(phi + atom);
    const float gm = __ldg(gamma + atom);

    const int   c    = __float2int_rn(__fmul_rn(tu, SR_F));  // jnp.round match
    const float r    = __fmul_rn(5.0f, sg);
    const float om_w = __fmul_rn(TWO_PI_F, om);              // rad/s
    const float g_w  = __fmul_rn(PI_F, gm);                  // rad/s^2
    const float inv_sg = __frcp_rn(sg);
    const float envc   = -__fmul_rn(HALF_LOG2E, __fmul_rn(inv_sg, inv_sg));
    const float l2a    = __log2f(fabsf(a));                  // fold |a| into ex2
    const float ph2    = (a < 0.0f) ? __fadd_rn(ph, PI_F) : ph;  // fold sign(a)

    // Conservative window (+/-2 pad covers all fp slop; boundary fuzz is
    // ~e^-12.5 in env, negligible), clamped to buffer and static window.
    const float delta0 = fmaf((float)c, INV_SR_F, -tu);
    int jlo = (int)ceilf ((-r - delta0) * SR_F) - 2;
    int jhi = (int)floorf(( r - delta0) * SR_F) + 2;
    jlo = max(jlo, max(-HALF_STATIC, -c));
    jhi = min(jhi, min( HALF_STATIC, num_samples - 1 - c));
    if (jlo > jhi) return;

    const int lo4 = (c + jlo) & ~3;     // 4-aligned vector start (>= 0)
    const int hi4 = (c + jhi) & ~3;     // last vector start (hi4+3 <= 239999)

    for (int i0 = lo4 + 4 * lane; i0 <= hi4; i0 += 4 * 32) {
        const float4 tv = __ldg(reinterpret_cast<const float4*>(g_t_table + i0));
        float4 val;
        val.x = gabor_eval(tv.x, tu, envc, l2a, om_w, g_w, ph2);
        val.y = gabor_eval(tv.y, tu, envc, l2a, om_w, g_w, ph2);
        val.z = gabor_eval(tv.z, tu, envc, l2a, om_w, g_w, ph2);
        val.w = gabor_eval(tv.w, tu, envc, l2a, om_w, g_w, ph2);
        atomicAdd(reinterpret_cast<float4*>(out + i0), val);   // RED.128
    }
}

extern "C" void kernel_launch(void* const* d_in, const int* in_sizes, int n_in,
                              void* d_out, int out_size) {
    const float* amplitude = (const float*)d_in[0];
    const float* tau       = (const float*)d_in[1];
    const float* omega     = (const float*)d_in[2];
    const float* sigma     = (const float*)d_in[3];
    const float* phi       = (const float*)d_in[4];
    const float* gamma     = (const float*)d_in[5];
    float* out = (float*)d_out;

    const int num_atoms   = in_sizes[0];     // 16384
    const int num_samples = out_size;        // 240000

    {
        int n4 = num_samples / 4;
        int threads = 256;
        int blocks  = (n4 + threads - 1) / threads;
        gabor_init_kernel<<<blocks, threads>>>((float4*)out, n4);
    }
    gabor_render_kernel<<<num_atoms / ATOMS_PER_BLOCK, THREADS>>>(
        amplitude, tau, omega, sigma, phi, gamma, out, num_samples);
}